// round 1
// baseline (speedup 1.0000x reference)
#include <cuda_runtime.h>

// Problem constants
#define BATCH 8
#define TT 2048
#define CH 512          // IN_CH = KEY = VAL = 512
#define MTOT (BATCH*TT) // 16384
#define NTILES (TT/128) // 16 row/col tiles per batch
#define INV_SQRTK 0.04419417382415922f  // 1/sqrt(512)

// Scratch (device globals; no allocation allowed)
__device__ float g_q[(size_t)MTOT * CH];
__device__ float g_k[(size_t)MTOT * CH];
__device__ float g_v[(size_t)MTOT * CH];
__device__ float g_E[(size_t)BATCH * TT * TT];        // 134 MB
__device__ float g_part[BATCH * NTILES * TT];         // per-(b, rowtile) column partial sums
__device__ float g_rcol[BATCH * TT];                  // 1/colsum

// ---------------------------------------------------------------------------
// Kernel 1: QKV projection.  C[m,n] = sum_k x[m,k]*W[k,n] + bias[n]
// 128x128x8 tile, 256 threads, 8x8 microtile. blockIdx.z selects q/k/v.
// ---------------------------------------------------------------------------
__global__ __launch_bounds__(256) void proj_kernel(
    const float* __restrict__ x,
    const float* __restrict__ Wq, const float* __restrict__ bq,
    const float* __restrict__ Wk, const float* __restrict__ bk,
    const float* __restrict__ Wv, const float* __restrict__ bv)
{
    const float* W; const float* bias; float* out;
    if (blockIdx.z == 0)      { W = Wq; bias = bq; out = g_q; }
    else if (blockIdx.z == 1) { W = Wk; bias = bk; out = g_k; }
    else                      { W = Wv; bias = bv; out = g_v; }

    __shared__ float As[8][128];
    __shared__ float Bs[8][128];

    const int tid = threadIdx.x;
    const int tx = tid & 15, ty = tid >> 4;
    const int m0 = blockIdx.y * 128, n0 = blockIdx.x * 128;

    const int arow = tid >> 1, ac4 = (tid & 1) * 4;   // A: 128 rows x 8 cols
    const int brow = tid >> 5, bc4 = (tid & 31) * 4;  // B: 8 rows x 128 cols

    const float* aptr = x + (size_t)(m0 + arow) * CH + ac4;
    const float* bptr = W + (size_t)brow * CH + n0 + bc4;

    float acc[8][8];
    #pragma unroll
    for (int i = 0; i < 8; i++)
        #pragma unroll
        for (int j = 0; j < 8; j++) acc[i][j] = 0.f;

    for (int k0 = 0; k0 < CH; k0 += 8) {
        float4 a  = *(const float4*)(aptr + k0);
        float4 bb = *(const float4*)(bptr + (size_t)k0 * CH);
        __syncthreads();
        As[ac4+0][arow] = a.x; As[ac4+1][arow] = a.y;
        As[ac4+2][arow] = a.z; As[ac4+3][arow] = a.w;
        *(float4*)&Bs[brow][bc4] = bb;
        __syncthreads();
        #pragma unroll
        for (int k = 0; k < 8; k++) {
            float af[8], bf[8];
            #pragma unroll
            for (int i = 0; i < 8; i++) af[i] = As[k][ty*8+i];
            #pragma unroll
            for (int j = 0; j < 8; j++) bf[j] = Bs[k][tx*8+j];
            #pragma unroll
            for (int i = 0; i < 8; i++)
                #pragma unroll
                for (int j = 0; j < 8; j++)
                    acc[i][j] = fmaf(af[i], bf[j], acc[i][j]);
        }
    }

    float bj[8];
    #pragma unroll
    for (int j = 0; j < 8; j++) bj[j] = bias[n0 + tx*8 + j];
    #pragma unroll
    for (int i = 0; i < 8; i++) {
        float* orow = out + (size_t)(m0 + ty*8 + i) * CH + n0 + tx*8;
        #pragma unroll
        for (int j = 0; j < 8; j++) orow[j] = acc[i][j] + bj[j];
    }
}

// ---------------------------------------------------------------------------
// Kernel 2: causal scores. For lower-triangular tiles (it >= is):
//   E[t,s] = (s<=t) ? exp((q[t]·k[s]) * INV_SQRTK) : 0
// Also emits per-(b, it) column partial sums (deterministic, no atomics).
// ---------------------------------------------------------------------------
__global__ __launch_bounds__(256) void scores_kernel()
{
    const int b = blockIdx.y;
    int idx = blockIdx.x;                 // 0..135 (lower-triangular tile index)
    int it = 0;
    while ((it + 1) * (it + 2) / 2 <= idx) it++;
    const int is = idx - it * (it + 1) / 2;
    const int t0 = it * 128, s0 = is * 128;

    const float* q  = g_q + (size_t)b * TT * CH;
    const float* km = g_k + (size_t)b * TT * CH;
    float* E        = g_E + (size_t)b * TT * TT;

    __shared__ float As[8][128];
    __shared__ float Bs[8][128];
    __shared__ float red[16][128];

    const int tid = threadIdx.x;
    const int tx = tid & 15, ty = tid >> 4;
    const int arow = tid >> 1, ac4 = (tid & 1) * 4;

    const float* aptr = q  + (size_t)(t0 + arow) * CH + ac4;
    const float* bptr = km + (size_t)(s0 + arow) * CH + ac4;

    float acc[8][8];
    #pragma unroll
    for (int i = 0; i < 8; i++)
        #pragma unroll
        for (int j = 0; j < 8; j++) acc[i][j] = 0.f;

    for (int k0 = 0; k0 < CH; k0 += 8) {
        float4 a  = *(const float4*)(aptr + k0);
        float4 bb = *(const float4*)(bptr + k0);
        __syncthreads();
        As[ac4+0][arow] = a.x;  As[ac4+1][arow] = a.y;
        As[ac4+2][arow] = a.z;  As[ac4+3][arow] = a.w;
        Bs[ac4+0][arow] = bb.x; Bs[ac4+1][arow] = bb.y;
        Bs[ac4+2][arow] = bb.z; Bs[ac4+3][arow] = bb.w;
        __syncthreads();
        #pragma unroll
        for (int k = 0; k < 8; k++) {
            float af[8], bf[8];
            #pragma unroll
            for (int i = 0; i < 8; i++) af[i] = As[k][ty*8+i];
            #pragma unroll
            for (int j = 0; j < 8; j++) bf[j] = Bs[k][tx*8+j];
            #pragma unroll
            for (int i = 0; i < 8; i++)
                #pragma unroll
                for (int j = 0; j < 8; j++)
                    acc[i][j] = fmaf(af[i], bf[j], acc[i][j]);
        }
    }

    float colpart[8];
    #pragma unroll
    for (int j = 0; j < 8; j++) colpart[j] = 0.f;

    #pragma unroll
    for (int i = 0; i < 8; i++) {
        const int t = t0 + ty*8 + i;
        float* erow = E + (size_t)t * TT + s0 + tx*8;
        #pragma unroll
        for (int j = 0; j < 8; j++) {
            const int s = s0 + tx*8 + j;
            float val = (s <= t) ? __expf(acc[i][j] * INV_SQRTK) : 0.f;
            erow[j] = val;
            colpart[j] += val;
        }
    }
    #pragma unroll
    for (int j = 0; j < 8; j++) red[ty][tx*8 + j] = colpart[j];
    __syncthreads();
    if (tid < 128) {
        float s = 0.f;
        #pragma unroll
        for (int r = 0; r < 16; r++) s += red[r][tid];
        g_part[((b * NTILES + it) * TT) + s0 + tid] = s;
    }
}

// ---------------------------------------------------------------------------
// Kernel 3: reduce column partials -> reciprocal colsum
// ---------------------------------------------------------------------------
__global__ void colsum_kernel()
{
    const int i = blockIdx.x * blockDim.x + threadIdx.x;  // 0..BATCH*TT-1
    if (i >= BATCH * TT) return;
    const int b = i >> 11, s = i & (TT - 1);
    float sum = 0.f;
    for (int it = s >> 7; it < NTILES; it++)
        sum += g_part[((b * NTILES + it) * TT) + s];
    g_rcol[i] = 1.0f / sum;
}

// ---------------------------------------------------------------------------
// Kernel 4: read[t,:] = sum_{s<=t} E[t,s]*rcol[s]*v[s,:]  -> out[:, 512:1024]
// GEMM over variable K extent (causal): s in [0, (it+1)*128)
// ---------------------------------------------------------------------------
__global__ __launch_bounds__(256) void read_kernel(float* __restrict__ out)
{
    const int b = blockIdx.z, it = blockIdx.y;
    const int t0 = it * 128, n0 = blockIdx.x * 128;

    const float* E    = g_E + (size_t)b * TT * TT;
    const float* v    = g_v + (size_t)b * TT * CH;
    const float* rcol = g_rcol + b * TT;

    __shared__ float As[8][128];
    __shared__ float Bs[8][128];

    const int tid = threadIdx.x;
    const int tx = tid & 15, ty = tid >> 4;
    const int arow = tid >> 1, ac4 = (tid & 1) * 4;
    const int brow = tid >> 5, bc4 = (tid & 31) * 4;

    float acc[8][8];
    #pragma unroll
    for (int i = 0; i < 8; i++)
        #pragma unroll
        for (int j = 0; j < 8; j++) acc[i][j] = 0.f;

    const int smax = (it + 1) * 128;
    for (int s0 = 0; s0 < smax; s0 += 8) {
        float4 a  = *(const float4*)(E + (size_t)(t0 + arow) * TT + s0 + ac4);
        float4 bb = *(const float4*)(v + (size_t)(s0 + brow) * CH + n0 + bc4);
        const float rs = rcol[s0 + brow];
        __syncthreads();
        As[ac4+0][arow] = a.x; As[ac4+1][arow] = a.y;
        As[ac4+2][arow] = a.z; As[ac4+3][arow] = a.w;
        Bs[brow][bc4+0] = bb.x * rs; Bs[brow][bc4+1] = bb.y * rs;
        Bs[brow][bc4+2] = bb.z * rs; Bs[brow][bc4+3] = bb.w * rs;
        __syncthreads();
        #pragma unroll
        for (int k = 0; k < 8; k++) {
            float af[8], bf[8];
            #pragma unroll
            for (int i = 0; i < 8; i++) af[i] = As[k][ty*8+i];
            #pragma unroll
            for (int j = 0; j < 8; j++) bf[j] = Bs[k][tx*8+j];
            #pragma unroll
            for (int i = 0; i < 8; i++)
                #pragma unroll
                for (int j = 0; j < 8; j++)
                    acc[i][j] = fmaf(af[i], bf[j], acc[i][j]);
        }
    }

    #pragma unroll
    for (int i = 0; i < 8; i++) {
        const int t = t0 + ty*8 + i;
        float* orow = out + (size_t)(b * TT + t) * 1024 + 512 + n0 + tx*8;
        #pragma unroll
        for (int j = 0; j < 8; j++) orow[j] = acc[i][j];
    }
}

// ---------------------------------------------------------------------------
// Kernel 5: copy x into out[:, 0:512]  (float4)
// ---------------------------------------------------------------------------
__global__ void copyx_kernel(const float* __restrict__ x, float* __restrict__ out)
{
    const int i = blockIdx.x * blockDim.x + threadIdx.x;  // over MTOT*128 float4
    if (i >= MTOT * 128) return;
    const int row = i >> 7, c4 = i & 127;
    float4 val = ((const float4*)x)[(size_t)row * 128 + c4];
    ((float4*)out)[(size_t)row * 256 + c4] = val;
}

// ---------------------------------------------------------------------------
extern "C" void kernel_launch(void* const* d_in, const int* in_sizes, int n_in,
                              void* d_out, int out_size)
{
    const float* x  = (const float*)d_in[0];
    const float* Wq = (const float*)d_in[1];
    const float* bq = (const float*)d_in[2];
    const float* Wk = (const float*)d_in[3];
    const float* bk = (const float*)d_in[4];
    const float* Wv = (const float*)d_in[5];
    const float* bv = (const float*)d_in[6];
    float* out = (float*)d_out;

    proj_kernel<<<dim3(4, 128, 3), 256>>>(x, Wq, bq, Wk, bk, Wv, bv);
    scores_kernel<<<dim3(136, BATCH), 256>>>();
    colsum_kernel<<<(BATCH * TT + 255) / 256, 256>>>();
    read_kernel<<<dim3(4, NTILES, BATCH), 256>>>(out);
    copyx_kernel<<<(MTOT * 128 + 255) / 256, 256>>>(x, out);
}

// round 4
// speedup vs baseline: 3.0107x; 3.0107x over previous
#include <cuda_runtime.h>
#include <cuda_bf16.h>
#include <cstdint>

// ---------------------------------------------------------------------------
// Problem constants
// ---------------------------------------------------------------------------
#define BATCH 8
#define TT 2048
#define CH 512
#define MTOT (BATCH*TT)          // 16384
#define NTILES (TT/128)          // 16
#define INV_SQRTK 0.04419417382415922f

// ---------------------------------------------------------------------------
// Shared memory layout (dynamic):
//   [0:1024)        reduction scratch (scores kernel)
//   [1024: +2*64KB) two stages x {Ahi, Alo, Bhi, Blo} tiles of 16KB each
// Tile = 128 rows x 128 bytes (64 bf16), SW128 swizzled.
// ---------------------------------------------------------------------------
#define SM_RED 0
#define SM_BUF 1024
#define T_BYTES 16384
#define STAGE_BYTES (4*T_BYTES)
#define SMEM_TOTAL (1024 + 2*STAGE_BYTES)   // 132096

// ---------------------------------------------------------------------------
// Device scratch (no allocation allowed)
// ---------------------------------------------------------------------------
__device__ __align__(16) __nv_bfloat16 g_xhi[(size_t)MTOT*CH];
__device__ __align__(16) __nv_bfloat16 g_xlo[(size_t)MTOT*CH];
__device__ __align__(16) __nv_bfloat16 g_wThi[(size_t)3*CH*CH];
__device__ __align__(16) __nv_bfloat16 g_wTlo[(size_t)3*CH*CH];
__device__ __align__(16) __nv_bfloat16 g_qhi[(size_t)MTOT*CH];
__device__ __align__(16) __nv_bfloat16 g_qlo[(size_t)MTOT*CH];
__device__ __align__(16) __nv_bfloat16 g_khi[(size_t)MTOT*CH];
__device__ __align__(16) __nv_bfloat16 g_klo[(size_t)MTOT*CH];
__device__ __align__(16) float         g_v[(size_t)MTOT*CH];
__device__ __align__(16) __nv_bfloat16 g_Ehi[(size_t)BATCH*TT*TT];
__device__ __align__(16) __nv_bfloat16 g_Elo[(size_t)BATCH*TT*TT];
__device__ __align__(16) __nv_bfloat16 g_vThi[(size_t)BATCH*CH*TT];
__device__ __align__(16) __nv_bfloat16 g_vTlo[(size_t)BATCH*CH*TT];
__device__ float g_part[BATCH*NTILES*TT];
__device__ float g_rcol[BATCH*TT];

// ---------------------------------------------------------------------------
// PTX helpers — all portable (sm_80-level) PTX, legal at compute_103
// ---------------------------------------------------------------------------
__device__ __forceinline__ uint32_t smem_u32(const void* p) {
    uint32_t a;
    asm("{ .reg .u64 t; cvta.to.shared.u64 t, %1; cvt.u32.u64 %0, t; }"
        : "=r"(a) : "l"(p));
    return a;
}

__device__ __forceinline__ void cp16(uint32_t s, const void* g) {
    asm volatile("cp.async.cg.shared.global [%0], [%1], 16;" :: "r"(s), "l"(g));
}
__device__ __forceinline__ void cp_commit() {
    asm volatile("cp.async.commit_group;" ::: "memory");
}
template<int N> __device__ __forceinline__ void cp_wait() {
    asm volatile("cp.async.wait_group %0;" :: "n"(N) : "memory");
}

__device__ __forceinline__ void ldm4(uint32_t* r, uint32_t a) {
    asm volatile("ldmatrix.sync.aligned.m8n8.x4.shared.b16 {%0,%1,%2,%3}, [%4];"
        : "=r"(r[0]), "=r"(r[1]), "=r"(r[2]), "=r"(r[3]) : "r"(a));
}

__device__ __forceinline__ void mma16816(float* c, const uint32_t* a, const uint32_t* b) {
    asm volatile(
        "mma.sync.aligned.m16n8k16.row.col.f32.bf16.bf16.f32 "
        "{%0,%1,%2,%3}, {%4,%5,%6,%7}, {%8,%9}, {%0,%1,%2,%3};"
        : "+f"(c[0]), "+f"(c[1]), "+f"(c[2]), "+f"(c[3])
        : "r"(a[0]), "r"(a[1]), "r"(a[2]), "r"(a[3]), "r"(b[0]), "r"(b[1]));
}

__device__ __forceinline__ void split_f32(float v, __nv_bfloat16& h, __nv_bfloat16& l) {
    h = __float2bfloat16(v);
    l = __float2bfloat16(v - __bfloat162float(h));
}

// ---------------------------------------------------------------------------
// Stage loader: 4 tiles of 128x64 bf16, SW128 swizzle, via cp.async
// ---------------------------------------------------------------------------
__device__ __forceinline__ void load_stage(
    uint32_t sbuf,
    const __nv_bfloat16* __restrict__ aHi, const __nv_bfloat16* __restrict__ aLo, int lda,
    const __nv_bfloat16* __restrict__ bHi, const __nv_bfloat16* __restrict__ bLo, int ldb,
    int kofs, int tid)
{
    #pragma unroll
    for (int i = 0; i < 4; i++) {
        const int u = tid + i*256;
        const int row = u >> 3, cg = u & 7;
        const uint32_t so = (uint32_t)(row*128) + (uint32_t)((cg*16) ^ ((row & 7) << 4));
        const size_t ga = (size_t)row * lda + kofs + cg*8;
        const size_t gb = (size_t)row * ldb + kofs + cg*8;
        cp16(sbuf + 0*T_BYTES + so, aHi + ga);
        cp16(sbuf + 1*T_BYTES + so, aLo + ga);
        cp16(sbuf + 2*T_BYTES + so, bHi + gb);
        cp16(sbuf + 3*T_BYTES + so, bLo + gb);
    }
}

// ---------------------------------------------------------------------------
// Compute one K=64 stage: 3 bf16-split passes via mma.sync
// Warp grid 2(M)x4(N); warp tile 64x32; acc[4][4][4] (m16 x n8 frags)
// ---------------------------------------------------------------------------
__device__ __forceinline__ void compute_stage(uint32_t sbuf, float acc[4][4][4],
                                              int lane, int wm, int wn)
{
    const int arow = wm*64 + (lane & 15);
    const uint32_t aX = (uint32_t)(lane & 16);
    const int brow = wn*32 + (lane & 7) + ((lane & 16) >> 1);
    const uint32_t bX = (uint32_t)((lane & 8) << 1);
    const uint32_t axor = (uint32_t)((arow & 7) << 4);
    const uint32_t bxor = (uint32_t)((lane & 7) << 4);

    #pragma unroll
    for (int kk = 0; kk < 4; kk++) {
        const uint32_t kb = kk*32;
        const uint32_t acol = (kb + aX) ^ axor;
        const uint32_t bcol = (kb + bX) ^ bxor;
        uint32_t ah[4][4], al[4][4], bb[2][4];
        #pragma unroll
        for (int mi = 0; mi < 4; mi++) {
            const uint32_t base = sbuf + (uint32_t)((arow + mi*16)*128) + acol;
            ldm4(ah[mi], base + 0*T_BYTES);
            ldm4(al[mi], base + 1*T_BYTES);
        }
        #pragma unroll
        for (int g = 0; g < 2; g++)
            ldm4(bb[g], sbuf + 2*T_BYTES + (uint32_t)((brow + g*16)*128) + bcol);
        #pragma unroll
        for (int mi = 0; mi < 4; mi++)
            #pragma unroll
            for (int nj = 0; nj < 4; nj++)
                mma16816(acc[mi][nj], ah[mi], &bb[nj>>1][(nj&1)*2]);   // hi*hi
        #pragma unroll
        for (int mi = 0; mi < 4; mi++)
            #pragma unroll
            for (int nj = 0; nj < 4; nj++)
                mma16816(acc[mi][nj], al[mi], &bb[nj>>1][(nj&1)*2]);   // lo*hi
        #pragma unroll
        for (int g = 0; g < 2; g++)
            ldm4(bb[g], sbuf + 3*T_BYTES + (uint32_t)((brow + g*16)*128) + bcol);
        #pragma unroll
        for (int mi = 0; mi < 4; mi++)
            #pragma unroll
            for (int nj = 0; nj < 4; nj++)
                mma16816(acc[mi][nj], ah[mi], &bb[nj>>1][(nj&1)*2]);   // hi*lo
    }
}

// ---------------------------------------------------------------------------
// Double-buffered mainloop (K = NC*64)
// ---------------------------------------------------------------------------
__device__ __forceinline__ void gemm_mainloop(
    const __nv_bfloat16* __restrict__ aHi, const __nv_bfloat16* __restrict__ aLo, int lda,
    const __nv_bfloat16* __restrict__ bHi, const __nv_bfloat16* __restrict__ bLo, int ldb,
    int NC, uint32_t sbase, float acc[4][4][4], int tid)
{
    const int lane = tid & 31, w = tid >> 5;
    const int wm = w >> 2, wn = w & 3;

    load_stage(sbase + SM_BUF, aHi, aLo, lda, bHi, bLo, ldb, 0, tid);
    cp_commit();

    for (int c = 0; c < NC; c++) {
        const uint32_t cur = sbase + SM_BUF + (uint32_t)(c & 1) * STAGE_BYTES;
        if (c + 1 < NC)
            load_stage(sbase + SM_BUF + (uint32_t)((c+1) & 1) * STAGE_BYTES,
                       aHi, aLo, lda, bHi, bLo, ldb, (c+1)*64, tid);
        cp_commit();
        cp_wait<1>();
        __syncthreads();
        compute_stage(cur, acc, lane, wm, wn);
        __syncthreads();
    }
}

// ---------------------------------------------------------------------------
extern __shared__ char dynsmem[];

// Kernel: QKV projection. grid(4 ntile, 128 mtile, 3 qkv)
__global__ __launch_bounds__(256, 1)
void proj_tc(const float* __restrict__ bq, const float* __restrict__ bk,
             const float* __restrict__ bv)
{
    const int z = blockIdx.z;
    const int m0 = blockIdx.y * 128, n0 = blockIdx.x * 128;
    const uint32_t sbase = smem_u32(dynsmem);
    const int tid = threadIdx.x;

    float acc[4][4][4];
    #pragma unroll
    for (int a = 0; a < 4; a++)
        #pragma unroll
        for (int b = 0; b < 4; b++)
            #pragma unroll
            for (int c = 0; c < 4; c++) acc[a][b][c] = 0.f;

    const __nv_bfloat16* aHi = g_xhi + (size_t)m0 * CH;
    const __nv_bfloat16* aLo = g_xlo + (size_t)m0 * CH;
    const __nv_bfloat16* bHi = g_wThi + (size_t)z*CH*CH + (size_t)n0 * CH;
    const __nv_bfloat16* bLo = g_wTlo + (size_t)z*CH*CH + (size_t)n0 * CH;

    gemm_mainloop(aHi, aLo, CH, bHi, bLo, CH, CH/64, sbase, acc, tid);

    const float* bias = (z == 0) ? bq : (z == 1) ? bk : bv;
    const int lane = tid & 31, w = tid >> 5;
    const int wm = w >> 2, wn = w & 3;

    #pragma unroll
    for (int mi = 0; mi < 4; mi++) {
        const int r0 = m0 + wm*64 + mi*16 + (lane >> 2);
        #pragma unroll
        for (int nj = 0; nj < 4; nj++) {
            const int n = n0 + wn*32 + nj*8 + (lane & 3)*2;
            const float b0 = bias[n], b1 = bias[n+1];
            const float v00 = acc[mi][nj][0] + b0, v01 = acc[mi][nj][1] + b1;
            const float v10 = acc[mi][nj][2] + b0, v11 = acc[mi][nj][3] + b1;
            if (z < 2) {
                __nv_bfloat16* oHi = (z == 0) ? g_qhi : g_khi;
                __nv_bfloat16* oLo = (z == 0) ? g_qlo : g_klo;
                __nv_bfloat16 h0,l0,h1,l1,h2,l2,h3,l3;
                split_f32(v00,h0,l0); split_f32(v01,h1,l1);
                split_f32(v10,h2,l2); split_f32(v11,h3,l3);
                *(__nv_bfloat162*)(oHi + (size_t)r0*CH + n)     = __nv_bfloat162(h0,h1);
                *(__nv_bfloat162*)(oLo + (size_t)r0*CH + n)     = __nv_bfloat162(l0,l1);
                *(__nv_bfloat162*)(oHi + (size_t)(r0+8)*CH + n) = __nv_bfloat162(h2,h3);
                *(__nv_bfloat162*)(oLo + (size_t)(r0+8)*CH + n) = __nv_bfloat162(l2,l3);
            } else {
                *(float2*)(g_v + (size_t)r0*CH + n)     = make_float2(v00, v01);
                *(float2*)(g_v + (size_t)(r0+8)*CH + n) = make_float2(v10, v11);
            }
        }
    }
}

// Kernel: causal scores -> exp -> E hi/lo + column partial sums.
// grid(136 tri-tiles, 8 batch)
__global__ __launch_bounds__(256, 1)
void scores_tc()
{
    const int b = blockIdx.y;
    int idx = blockIdx.x;
    int it = 0;
    while ((it + 1) * (it + 2) / 2 <= idx) it++;
    const int is = idx - it * (it + 1) / 2;
    const int t0 = it * 128, s0 = is * 128;

    const uint32_t sbase = smem_u32(dynsmem);
    const int tid = threadIdx.x;

    float acc[4][4][4];
    #pragma unroll
    for (int a = 0; a < 4; a++)
        #pragma unroll
        for (int c = 0; c < 4; c++)
            #pragma unroll
            for (int d = 0; d < 4; d++) acc[a][c][d] = 0.f;

    gemm_mainloop(g_qhi + ((size_t)b*TT + t0)*CH, g_qlo + ((size_t)b*TT + t0)*CH, CH,
                  g_khi + ((size_t)b*TT + s0)*CH, g_klo + ((size_t)b*TT + s0)*CH, CH,
                  CH/64, sbase, acc, tid);

    const int lane = tid & 31, w = tid >> 5;
    const int wm = w >> 2, wn = w & 3;
    float* red = (float*)dynsmem;   // [2][128]

    float psum[4][2];
    #pragma unroll
    for (int nj = 0; nj < 4; nj++) { psum[nj][0] = 0.f; psum[nj][1] = 0.f; }

    const bool diag = (it == is);
    #pragma unroll
    for (int mi = 0; mi < 4; mi++) {
        const int ta = t0 + wm*64 + mi*16 + (lane >> 2);
        const int tb = ta + 8;
        #pragma unroll
        for (int nj = 0; nj < 4; nj++) {
            const int s = s0 + wn*32 + nj*8 + (lane & 3)*2;
            float e00 = __expf(acc[mi][nj][0] * INV_SQRTK);
            float e01 = __expf(acc[mi][nj][1] * INV_SQRTK);
            float e10 = __expf(acc[mi][nj][2] * INV_SQRTK);
            float e11 = __expf(acc[mi][nj][3] * INV_SQRTK);
            if (diag) {
                if (s   > ta) e00 = 0.f;
                if (s+1 > ta) e01 = 0.f;
                if (s   > tb) e10 = 0.f;
                if (s+1 > tb) e11 = 0.f;
            }
            __nv_bfloat16 h0,l0,h1,l1,h2,l2,h3,l3;
            split_f32(e00,h0,l0); split_f32(e01,h1,l1);
            split_f32(e10,h2,l2); split_f32(e11,h3,l3);
            const size_t oa = ((size_t)b*TT + ta)*TT + s;
            const size_t ob = ((size_t)b*TT + tb)*TT + s;
            *(__nv_bfloat162*)(g_Ehi + oa) = __nv_bfloat162(h0,h1);
            *(__nv_bfloat162*)(g_Elo + oa) = __nv_bfloat162(l0,l1);
            *(__nv_bfloat162*)(g_Ehi + ob) = __nv_bfloat162(h2,h3);
            *(__nv_bfloat162*)(g_Elo + ob) = __nv_bfloat162(l2,l3);
            psum[nj][0] += e00 + e10;
            psum[nj][1] += e01 + e11;
        }
    }
    // reduce across lanes with identical (lane&3)
    #pragma unroll
    for (int ofs = 4; ofs <= 16; ofs <<= 1)
        #pragma unroll
        for (int nj = 0; nj < 4; nj++) {
            psum[nj][0] += __shfl_xor_sync(0xffffffff, psum[nj][0], ofs);
            psum[nj][1] += __shfl_xor_sync(0xffffffff, psum[nj][1], ofs);
        }
    __syncthreads();   // dynsmem stage area no longer needed; reuse header
    if (lane < 4) {
        #pragma unroll
        for (int nj = 0; nj < 4; nj++) {
            const int col = wn*32 + nj*8 + lane*2;
            red[wm*128 + col]     = psum[nj][0];
            red[wm*128 + col + 1] = psum[nj][1];
        }
    }
    __syncthreads();
    if (tid < 128)
        g_part[(size_t)(b*NTILES + it)*TT + s0 + tid] = red[tid] + red[128 + tid];
}

// Kernel: reduce column partials -> reciprocal colsum
__global__ void colsum_kernel()
{
    const int i = blockIdx.x * blockDim.x + threadIdx.x;  // b*TT + s
    if (i >= BATCH*TT) return;
    const int b = i >> 11, s = i & (TT - 1);
    float sum = 0.f;
    for (int it = s >> 7; it < NTILES; it++)
        sum += g_part[(size_t)(b*NTILES + it)*TT + s];
    g_rcol[i] = 1.0f / sum;
}

// Kernel: v -> vT scaled by rcol, bf16 hi/lo. grid(64 s-tiles, 16 n-tiles, 8)
__global__ void convvt_kernel()
{
    __shared__ float tile[32][33];
    const int b = blockIdx.z;
    const int s0 = blockIdx.x * 32, n0 = blockIdx.y * 32;
    const int tx = threadIdx.x, ty = threadIdx.y;
    const int s = s0 + ty;
    const float scale = g_rcol[b*TT + s];
    tile[ty][tx] = g_v[((size_t)b*TT + s) * CH + n0 + tx] * scale;
    __syncthreads();
    const float v = tile[tx][ty];
    __nv_bfloat16 h, l;
    split_f32(v, h, l);
    const size_t o = ((size_t)b*CH + n0 + ty) * TT + s0 + tx;
    g_vThi[o] = h;
    g_vTlo[o] = l;
}

// Kernel: read = E * vT'. grid(4 ntile, 16 ttile, 8 batch)
__global__ __launch_bounds__(256, 1)
void read_tc(float* __restrict__ out)
{
    const int b = blockIdx.z, it = blockIdx.y;
    const int t0 = it * 128, n0 = blockIdx.x * 128;
    const uint32_t sbase = smem_u32(dynsmem);
    const int tid = threadIdx.x;

    float acc[4][4][4];
    #pragma unroll
    for (int a = 0; a < 4; a++)
        #pragma unroll
        for (int c = 0; c < 4; c++)
            #pragma unroll
            for (int d = 0; d < 4; d++) acc[a][c][d] = 0.f;

    gemm_mainloop(g_Ehi + ((size_t)b*TT + t0)*TT, g_Elo + ((size_t)b*TT + t0)*TT, TT,
                  g_vThi + ((size_t)b*CH + n0)*TT, g_vTlo + ((size_t)b*CH + n0)*TT, TT,
                  (it + 1) * 2, sbase, acc, tid);

    const int lane = tid & 31, w = tid >> 5;
    const int wm = w >> 2, wn = w & 3;

    #pragma unroll
    for (int mi = 0; mi < 4; mi++) {
        const int t = t0 + wm*64 + mi*16 + (lane >> 2);
        #pragma unroll
        for (int nj = 0; nj < 4; nj++) {
            const int n = n0 + wn*32 + nj*8 + (lane & 3)*2;
            float* oa = out + ((size_t)(b*TT + t)) * 1024 + 512 + n;
            float* ob = out + ((size_t)(b*TT + t + 8)) * 1024 + 512 + n;
            *(float2*)oa = make_float2(acc[mi][nj][0], acc[mi][nj][1]);
            *(float2*)ob = make_float2(acc[mi][nj][2], acc[mi][nj][3]);
        }
    }
}

// ---------------------------------------------------------------------------
// Conversion kernels
// ---------------------------------------------------------------------------
__global__ void convx_kernel(const float* __restrict__ x)
{
    const size_t i = (size_t)blockIdx.x * blockDim.x + threadIdx.x;  // float4 idx
    const float4 v = ((const float4*)x)[i];
    __align__(8) __nv_bfloat16 h[4], l[4];
    split_f32(v.x, h[0], l[0]);
    split_f32(v.y, h[1], l[1]);
    split_f32(v.z, h[2], l[2]);
    split_f32(v.w, h[3], l[3]);
    ((uint2*)g_xhi)[i] = *(const uint2*)h;
    ((uint2*)g_xlo)[i] = *(const uint2*)l;
}

__global__ void convw_kernel(const float* __restrict__ Wq,
                             const float* __restrict__ Wk,
                             const float* __restrict__ Wv)
{
    __shared__ float tile[32][33];
    const float* W = (blockIdx.z == 0) ? Wq : (blockIdx.z == 1) ? Wk : Wv;
    const int k0 = blockIdx.x * 32, n0 = blockIdx.y * 32;
    const int tx = threadIdx.x, ty = threadIdx.y;
    tile[ty][tx] = W[(size_t)(k0 + ty) * CH + n0 + tx];
    __syncthreads();
    const float v = tile[tx][ty];   // = W[k0+tx][n0+ty]
    __nv_bfloat16 h, l;
    split_f32(v, h, l);
    const size_t o = (size_t)blockIdx.z*CH*CH + (size_t)(n0 + ty) * CH + k0 + tx;
    g_wThi[o] = h;
    g_wTlo[o] = l;
}

__global__ void copyx_kernel(const float* __restrict__ x, float* __restrict__ out)
{
    const int i = blockIdx.x * blockDim.x + threadIdx.x;  // float4 index
    if (i >= MTOT * 128) return;
    const int row = i >> 7, c4 = i & 127;
    const float4 val = ((const float4*)x)[(size_t)row * 128 + c4];
    ((float4*)out)[(size_t)row * 256 + c4] = val;
}

// ---------------------------------------------------------------------------
extern "C" void kernel_launch(void* const* d_in, const int* in_sizes, int n_in,
                              void* d_out, int out_size)
{
    const float* x  = (const float*)d_in[0];
    const float* Wq = (const float*)d_in[1];
    const float* bq = (const float*)d_in[2];
    const float* Wk = (const float*)d_in[3];
    const float* bk = (const float*)d_in[4];
    const float* Wv = (const float*)d_in[5];
    const float* bv = (const float*)d_in[6];
    float* out = (float*)d_out;

    cudaFuncSetAttribute(proj_tc,   cudaFuncAttributeMaxDynamicSharedMemorySize, SMEM_TOTAL);
    cudaFuncSetAttribute(scores_tc, cudaFuncAttributeMaxDynamicSharedMemorySize, SMEM_TOTAL);
    cudaFuncSetAttribute(read_tc,   cudaFuncAttributeMaxDynamicSharedMemorySize, SMEM_TOTAL);

    convx_kernel<<<8192, 256>>>(x);
    convw_kernel<<<dim3(16, 16, 3), dim3(32, 32)>>>(Wq, Wk, Wv);
    proj_tc<<<dim3(4, 128, 3), 256, SMEM_TOTAL>>>(bq, bk, bv);
    scores_tc<<<dim3(136, BATCH), 256, SMEM_TOTAL>>>();
    colsum_kernel<<<64, 256>>>();
    convvt_kernel<<<dim3(64, 16, 8), dim3(32, 32)>>>();
    read_tc<<<dim3(4, NTILES, BATCH), 256, SMEM_TOTAL>>>(out);
    copyx_kernel<<<8192, 256>>>(x, out);
}

// round 6
// speedup vs baseline: 3.0755x; 1.0215x over previous
#include <cuda_runtime.h>
#include <cuda_bf16.h>
#include <cstdint>

// ---------------------------------------------------------------------------
// Problem constants
// ---------------------------------------------------------------------------
#define BATCH 8
#define TT 2048
#define CH 512
#define MTOT (BATCH*TT)          // 16384
#define NTILES (TT/128)          // 16
#define INV_SQRTK 0.04419417382415922f

// ---------------------------------------------------------------------------
// Shared memory layout (dynamic):
//   [0:1024)         reduction scratch (scores kernel)
//   [1024: +3*64KB)  three stages x {Ahi, Alo, Bhi, Blo} tiles of 16KB each
// Tile = 128 rows x 128 bytes (64 bf16), SW128 swizzled.
// ---------------------------------------------------------------------------
#define SM_RED 0
#define SM_BUF 1024
#define T_BYTES 16384
#define STAGE_BYTES (4*T_BYTES)
#define NSTAGE 3
#define SMEM_TOTAL (1024 + NSTAGE*STAGE_BYTES)   // 197632

// ---------------------------------------------------------------------------
// Device scratch (no allocation allowed)
// ---------------------------------------------------------------------------
__device__ __align__(16) __nv_bfloat16 g_xhi[(size_t)MTOT*CH];
__device__ __align__(16) __nv_bfloat16 g_xlo[(size_t)MTOT*CH];
__device__ __align__(16) __nv_bfloat16 g_wThi[(size_t)3*CH*CH];
__device__ __align__(16) __nv_bfloat16 g_wTlo[(size_t)3*CH*CH];
__device__ __align__(16) __nv_bfloat16 g_qhi[(size_t)MTOT*CH];
__device__ __align__(16) __nv_bfloat16 g_qlo[(size_t)MTOT*CH];
__device__ __align__(16) __nv_bfloat16 g_khi[(size_t)MTOT*CH];
__device__ __align__(16) __nv_bfloat16 g_klo[(size_t)MTOT*CH];
__device__ __align__(16) float         g_v[(size_t)MTOT*CH];
__device__ __align__(16) __nv_bfloat16 g_Ehi[(size_t)BATCH*TT*TT];
__device__ __align__(16) __nv_bfloat16 g_Elo[(size_t)BATCH*TT*TT];
__device__ __align__(16) __nv_bfloat16 g_vThi[(size_t)BATCH*CH*TT];
__device__ __align__(16) __nv_bfloat16 g_vTlo[(size_t)BATCH*CH*TT];
__device__ float g_part[BATCH*NTILES*TT];
__device__ float g_rcol[BATCH*TT];

// ---------------------------------------------------------------------------
// PTX helpers — portable (sm_80-level) PTX, legal at compute_103
// ---------------------------------------------------------------------------
__device__ __forceinline__ uint32_t smem_u32(const void* p) {
    uint32_t a;
    asm("{ .reg .u64 t; cvta.to.shared.u64 t, %1; cvt.u32.u64 %0, t; }"
        : "=r"(a) : "l"(p));
    return a;
}

__device__ __forceinline__ void cp16(uint32_t s, const void* g) {
    asm volatile("cp.async.cg.shared.global [%0], [%1], 16;" :: "r"(s), "l"(g));
}
__device__ __forceinline__ void cp_commit() {
    asm volatile("cp.async.commit_group;" ::: "memory");
}
template<int N> __device__ __forceinline__ void cp_wait() {
    asm volatile("cp.async.wait_group %0;" :: "n"(N) : "memory");
}

__device__ __forceinline__ void ldm4(uint32_t* r, uint32_t a) {
    asm volatile("ldmatrix.sync.aligned.m8n8.x4.shared.b16 {%0,%1,%2,%3}, [%4];"
        : "=r"(r[0]), "=r"(r[1]), "=r"(r[2]), "=r"(r[3]) : "r"(a));
}

__device__ __forceinline__ void mma16816(float* c, const uint32_t* a, const uint32_t* b) {
    asm volatile(
        "mma.sync.aligned.m16n8k16.row.col.f32.bf16.bf16.f32 "
        "{%0,%1,%2,%3}, {%4,%5,%6,%7}, {%8,%9}, {%0,%1,%2,%3};"
        : "+f"(c[0]), "+f"(c[1]), "+f"(c[2]), "+f"(c[3])
        : "r"(a[0]), "r"(a[1]), "r"(a[2]), "r"(a[3]), "r"(b[0]), "r"(b[1]));
}

__device__ __forceinline__ void split_f32(float v, __nv_bfloat16& h, __nv_bfloat16& l) {
    h = __float2bfloat16(v);
    l = __float2bfloat16(v - __bfloat162float(h));
}

// ---------------------------------------------------------------------------
// Stage loader: 4 tiles of 128x64 bf16, SW128 swizzle, via cp.async
// ---------------------------------------------------------------------------
__device__ __forceinline__ void load_stage(
    uint32_t sbuf,
    const __nv_bfloat16* __restrict__ aHi, const __nv_bfloat16* __restrict__ aLo, int lda,
    const __nv_bfloat16* __restrict__ bHi, const __nv_bfloat16* __restrict__ bLo, int ldb,
    int kofs, int tid)
{
    #pragma unroll
    for (int i = 0; i < 4; i++) {
        const int u = tid + i*256;
        const int row = u >> 3, cg = u & 7;
        const uint32_t so = (uint32_t)(row*128) + (uint32_t)((cg*16) ^ ((row & 7) << 4));
        const size_t ga = (size_t)row * lda + kofs + cg*8;
        const size_t gb = (size_t)row * ldb + kofs + cg*8;
        cp16(sbuf + 0*T_BYTES + so, aHi + ga);
        cp16(sbuf + 1*T_BYTES + so, aLo + ga);
        cp16(sbuf + 2*T_BYTES + so, bHi + gb);
        cp16(sbuf + 3*T_BYTES + so, bLo + gb);
    }
}

// ---------------------------------------------------------------------------
// Compute one K=64 stage: 3 bf16-split passes via mma.sync
// Warp grid 2(M)x4(N); warp tile 64x32; acc[4][4][4] (m16 x n8 frags)
// ---------------------------------------------------------------------------
__device__ __forceinline__ void compute_stage(uint32_t sbuf, float acc[4][4][4],
                                              int lane, int wm, int wn)
{
    const int arow = wm*64 + (lane & 15);
    const uint32_t aX = (uint32_t)(lane & 16);
    const int brow = wn*32 + (lane & 7) + ((lane & 16) >> 1);
    const uint32_t bX = (uint32_t)((lane & 8) << 1);
    const uint32_t axor = (uint32_t)((arow & 7) << 4);
    const uint32_t bxor = (uint32_t)((lane & 7) << 4);

    #pragma unroll
    for (int kk = 0; kk < 4; kk++) {
        const uint32_t kb = kk*32;
        const uint32_t acol = (kb + aX) ^ axor;
        const uint32_t bcol = (kb + bX) ^ bxor;
        uint32_t ah[4][4], al[4][4], bh[2][4], bl[2][4];
        #pragma unroll
        for (int g = 0; g < 2; g++) {
            const uint32_t bbase = (uint32_t)((brow + g*16)*128) + bcol;
            ldm4(bh[g], sbuf + 2*T_BYTES + bbase);
            ldm4(bl[g], sbuf + 3*T_BYTES + bbase);
        }
        #pragma unroll
        for (int mi = 0; mi < 4; mi++) {
            const uint32_t base = sbuf + (uint32_t)((arow + mi*16)*128) + acol;
            ldm4(ah[mi], base + 0*T_BYTES);
            ldm4(al[mi], base + 1*T_BYTES);
        }
        #pragma unroll
        for (int mi = 0; mi < 4; mi++)
            #pragma unroll
            for (int nj = 0; nj < 4; nj++)
                mma16816(acc[mi][nj], ah[mi], &bh[nj>>1][(nj&1)*2]);   // hi*hi
        #pragma unroll
        for (int mi = 0; mi < 4; mi++)
            #pragma unroll
            for (int nj = 0; nj < 4; nj++)
                mma16816(acc[mi][nj], al[mi], &bh[nj>>1][(nj&1)*2]);   // lo*hi
        #pragma unroll
        for (int mi = 0; mi < 4; mi++)
            #pragma unroll
            for (int nj = 0; nj < 4; nj++)
                mma16816(acc[mi][nj], ah[mi], &bl[nj>>1][(nj&1)*2]);   // hi*lo
    }
}

// ---------------------------------------------------------------------------
// 3-stage single-barrier pipelined mainloop (K = NC*64)
//   iter c: wait(stage c) -> barrier -> issue load(c+2) -> compute(c)
// Buffer for load(c+2) is stage (c-1)'s, provably free after the barrier.
// ---------------------------------------------------------------------------
__device__ __forceinline__ void gemm_mainloop(
    const __nv_bfloat16* __restrict__ aHi, const __nv_bfloat16* __restrict__ aLo, int lda,
    const __nv_bfloat16* __restrict__ bHi, const __nv_bfloat16* __restrict__ bLo, int ldb,
    int NC, uint32_t sbase, float acc[4][4][4], int tid)
{
    const int lane = tid & 31, w = tid >> 5;
    const int wm = w >> 2, wn = w & 3;

    // prologue: exactly two committed groups
    load_stage(sbase + SM_BUF, aHi, aLo, lda, bHi, bLo, ldb, 0, tid);
    cp_commit();
    if (NC > 1)
        load_stage(sbase + SM_BUF + STAGE_BYTES, aHi, aLo, lda, bHi, bLo, ldb, 64, tid);
    cp_commit();

    int s_cur = 0, s_nxt = 2 % NSTAGE;
    for (int c = 0; c < NC; c++) {
        cp_wait<1>();          // own copies for stage c complete
        __syncthreads();       // publish; also: all warps done with stage c-1
        if (c + 2 < NC)
            load_stage(sbase + SM_BUF + (uint32_t)s_nxt * STAGE_BYTES,
                       aHi, aLo, lda, bHi, bLo, ldb, (c+2)*64, tid);
        cp_commit();           // one group per iteration (possibly empty)
        compute_stage(sbase + SM_BUF + (uint32_t)s_cur * STAGE_BYTES, acc, lane, wm, wn);
        s_cur = (s_cur + 1 == NSTAGE) ? 0 : s_cur + 1;
        s_nxt = (s_nxt + 1 == NSTAGE) ? 0 : s_nxt + 1;
    }
    __syncthreads();           // protect epilogue smem reuse (scores)
}

// ---------------------------------------------------------------------------
extern __shared__ char dynsmem[];

// Kernel: QKV projection. grid(4 ntile, 128 mtile, 3 qkv)
__global__ __launch_bounds__(256, 1)
void proj_tc(const float* __restrict__ bq, const float* __restrict__ bk,
             const float* __restrict__ bv)
{
    const int z = blockIdx.z;
    const int m0 = blockIdx.y * 128, n0 = blockIdx.x * 128;
    const uint32_t sbase = smem_u32(dynsmem);
    const int tid = threadIdx.x;

    float acc[4][4][4];
    #pragma unroll
    for (int a = 0; a < 4; a++)
        #pragma unroll
        for (int b = 0; b < 4; b++)
            #pragma unroll
            for (int c = 0; c < 4; c++) acc[a][b][c] = 0.f;

    gemm_mainloop(g_xhi + (size_t)m0 * CH, g_xlo + (size_t)m0 * CH, CH,
                  g_wThi + (size_t)z*CH*CH + (size_t)n0 * CH,
                  g_wTlo + (size_t)z*CH*CH + (size_t)n0 * CH, CH,
                  CH/64, sbase, acc, tid);

    const float* bias = (z == 0) ? bq : (z == 1) ? bk : bv;
    const int lane = tid & 31, w = tid >> 5;
    const int wm = w >> 2, wn = w & 3;

    #pragma unroll
    for (int mi = 0; mi < 4; mi++) {
        const int r0 = m0 + wm*64 + mi*16 + (lane >> 2);
        #pragma unroll
        for (int nj = 0; nj < 4; nj++) {
            const int n = n0 + wn*32 + nj*8 + (lane & 3)*2;
            const float b0 = bias[n], b1 = bias[n+1];
            const float v00 = acc[mi][nj][0] + b0, v01 = acc[mi][nj][1] + b1;
            const float v10 = acc[mi][nj][2] + b0, v11 = acc[mi][nj][3] + b1;
            if (z < 2) {
                __nv_bfloat16* oHi = (z == 0) ? g_qhi : g_khi;
                __nv_bfloat16* oLo = (z == 0) ? g_qlo : g_klo;
                __nv_bfloat16 h0,l0,h1,l1,h2,l2,h3,l3;
                split_f32(v00,h0,l0); split_f32(v01,h1,l1);
                split_f32(v10,h2,l2); split_f32(v11,h3,l3);
                *(__nv_bfloat162*)(oHi + (size_t)r0*CH + n)     = __nv_bfloat162(h0,h1);
                *(__nv_bfloat162*)(oLo + (size_t)r0*CH + n)     = __nv_bfloat162(l0,l1);
                *(__nv_bfloat162*)(oHi + (size_t)(r0+8)*CH + n) = __nv_bfloat162(h2,h3);
                *(__nv_bfloat162*)(oLo + (size_t)(r0+8)*CH + n) = __nv_bfloat162(l2,l3);
            } else {
                *(float2*)(g_v + (size_t)r0*CH + n)     = make_float2(v00, v01);
                *(float2*)(g_v + (size_t)(r0+8)*CH + n) = make_float2(v10, v11);
            }
        }
    }
}

// Kernel: causal scores -> exp -> E hi/lo + column partial sums.
// grid(136 tri-tiles, 8 batch)
__global__ __launch_bounds__(256, 1)
void scores_tc()
{
    const int b = blockIdx.y;
    int idx = blockIdx.x;
    int it = 0;
    while ((it + 1) * (it + 2) / 2 <= idx) it++;
    const int is = idx - it * (it + 1) / 2;
    const int t0 = it * 128, s0 = is * 128;

    const uint32_t sbase = smem_u32(dynsmem);
    const int tid = threadIdx.x;

    float acc[4][4][4];
    #pragma unroll
    for (int a = 0; a < 4; a++)
        #pragma unroll
        for (int c = 0; c < 4; c++)
            #pragma unroll
            for (int d = 0; d < 4; d++) acc[a][c][d] = 0.f;

    gemm_mainloop(g_qhi + ((size_t)b*TT + t0)*CH, g_qlo + ((size_t)b*TT + t0)*CH, CH,
                  g_khi + ((size_t)b*TT + s0)*CH, g_klo + ((size_t)b*TT + s0)*CH, CH,
                  CH/64, sbase, acc, tid);

    const int lane = tid & 31, w = tid >> 5;
    const int wm = w >> 2, wn = w & 3;
    float* red = (float*)dynsmem;   // [2][128]

    float psum[4][2];
    #pragma unroll
    for (int nj = 0; nj < 4; nj++) { psum[nj][0] = 0.f; psum[nj][1] = 0.f; }

    const bool diag = (it == is);
    #pragma unroll
    for (int mi = 0; mi < 4; mi++) {
        const int ta = t0 + wm*64 + mi*16 + (lane >> 2);
        const int tb = ta + 8;
        #pragma unroll
        for (int nj = 0; nj < 4; nj++) {
            const int s = s0 + wn*32 + nj*8 + (lane & 3)*2;
            float e00 = __expf(acc[mi][nj][0] * INV_SQRTK);
            float e01 = __expf(acc[mi][nj][1] * INV_SQRTK);
            float e10 = __expf(acc[mi][nj][2] * INV_SQRTK);
            float e11 = __expf(acc[mi][nj][3] * INV_SQRTK);
            if (diag) {
                if (s   > ta) e00 = 0.f;
                if (s+1 > ta) e01 = 0.f;
                if (s   > tb) e10 = 0.f;
                if (s+1 > tb) e11 = 0.f;
            }
            __nv_bfloat16 h0,l0,h1,l1,h2,l2,h3,l3;
            split_f32(e00,h0,l0); split_f32(e01,h1,l1);
            split_f32(e10,h2,l2); split_f32(e11,h3,l3);
            const size_t oa = ((size_t)b*TT + ta)*TT + s;
            const size_t ob = ((size_t)b*TT + tb)*TT + s;
            *(__nv_bfloat162*)(g_Ehi + oa) = __nv_bfloat162(h0,h1);
            *(__nv_bfloat162*)(g_Elo + oa) = __nv_bfloat162(l0,l1);
            *(__nv_bfloat162*)(g_Ehi + ob) = __nv_bfloat162(h2,h3);
            *(__nv_bfloat162*)(g_Elo + ob) = __nv_bfloat162(l2,l3);
            psum[nj][0] += e00 + e10;
            psum[nj][1] += e01 + e11;
        }
    }
    // reduce across lanes with identical (lane&3)
    #pragma unroll
    for (int ofs = 4; ofs <= 16; ofs <<= 1)
        #pragma unroll
        for (int nj = 0; nj < 4; nj++) {
            psum[nj][0] += __shfl_xor_sync(0xffffffff, psum[nj][0], ofs);
            psum[nj][1] += __shfl_xor_sync(0xffffffff, psum[nj][1], ofs);
        }
    if (lane < 4) {
        #pragma unroll
        for (int nj = 0; nj < 4; nj++) {
            const int col = wn*32 + nj*8 + lane*2;
            red[wm*128 + col]     = psum[nj][0];
            red[wm*128 + col + 1] = psum[nj][1];
        }
    }
    __syncthreads();
    if (tid < 128)
        g_part[(size_t)(b*NTILES + it)*TT + s0 + tid] = red[tid] + red[128 + tid];
}

// Kernel: reduce column partials -> reciprocal colsum
__global__ void colsum_kernel()
{
    const int i = blockIdx.x * blockDim.x + threadIdx.x;  // b*TT + s
    if (i >= BATCH*TT) return;
    const int b = i >> 11, s = i & (TT - 1);
    float sum = 0.f;
    for (int it = s >> 7; it < NTILES; it++)
        sum += g_part[(size_t)(b*NTILES + it)*TT + s];
    g_rcol[i] = 1.0f / sum;
}

// Kernel: v -> vT scaled by rcol, bf16 hi/lo. grid(64 s-tiles, 16 n-tiles, 8)
__global__ void convvt_kernel()
{
    __shared__ float tile[32][33];
    const int b = blockIdx.z;
    const int s0 = blockIdx.x * 32, n0 = blockIdx.y * 32;
    const int tx = threadIdx.x, ty = threadIdx.y;
    const int s = s0 + ty;
    const float scale = g_rcol[b*TT + s];
    tile[ty][tx] = g_v[((size_t)b*TT + s) * CH + n0 + tx] * scale;
    __syncthreads();
    const float v = tile[tx][ty];
    __nv_bfloat16 h, l;
    split_f32(v, h, l);
    const size_t o = ((size_t)b*CH + n0 + ty) * TT + s0 + tx;
    g_vThi[o] = h;
    g_vTlo[o] = l;
}

// Kernel: read = E * vT'. grid(4 ntile, 16 ttile, 8 batch)
// it reversed so heavy (late-row) tiles launch first -> better wave balance.
__global__ __launch_bounds__(256, 1)
void read_tc(float* __restrict__ out)
{
    const int b = blockIdx.z;
    const int it = NTILES - 1 - blockIdx.y;
    const int t0 = it * 128, n0 = blockIdx.x * 128;
    const uint32_t sbase = smem_u32(dynsmem);
    const int tid = threadIdx.x;

    float acc[4][4][4];
    #pragma unroll
    for (int a = 0; a < 4; a++)
        #pragma unroll
        for (int c = 0; c < 4; c++)
            #pragma unroll
            for (int d = 0; d < 4; d++) acc[a][c][d] = 0.f;

    gemm_mainloop(g_Ehi + ((size_t)b*TT + t0)*TT, g_Elo + ((size_t)b*TT + t0)*TT, TT,
                  g_vThi + ((size_t)b*CH + n0)*TT, g_vTlo + ((size_t)b*CH + n0)*TT, TT,
                  (it + 1) * 2, sbase, acc, tid);

    const int lane = tid & 31, w = tid >> 5;
    const int wm = w >> 2, wn = w & 3;

    #pragma unroll
    for (int mi = 0; mi < 4; mi++) {
        const int t = t0 + wm*64 + mi*16 + (lane >> 2);
        #pragma unroll
        for (int nj = 0; nj < 4; nj++) {
            const int n = n0 + wn*32 + nj*8 + (lane & 3)*2;
            float* oa = out + ((size_t)(b*TT + t)) * 1024 + 512 + n;
            float* ob = out + ((size_t)(b*TT + t + 8)) * 1024 + 512 + n;
            *(float2*)oa = make_float2(acc[mi][nj][0], acc[mi][nj][1]);
            *(float2*)ob = make_float2(acc[mi][nj][2], acc[mi][nj][3]);
        }
    }
}

// ---------------------------------------------------------------------------
// Conversion kernels
// ---------------------------------------------------------------------------
__global__ void convx_kernel(const float* __restrict__ x)
{
    const size_t i = (size_t)blockIdx.x * blockDim.x + threadIdx.x;  // float4 idx
    const float4 v = ((const float4*)x)[i];
    __align__(8) __nv_bfloat16 h[4], l[4];
    split_f32(v.x, h[0], l[0]);
    split_f32(v.y, h[1], l[1]);
    split_f32(v.z, h[2], l[2]);
    split_f32(v.w, h[3], l[3]);
    ((uint2*)g_xhi)[i] = *(const uint2*)h;
    ((uint2*)g_xlo)[i] = *(const uint2*)l;
}

__global__ void convw_kernel(const float* __restrict__ Wq,
                             const float* __restrict__ Wk,
                             const float* __restrict__ Wv)
{
    __shared__ float tile[32][33];
    const float* W = (blockIdx.z == 0) ? Wq : (blockIdx.z == 1) ? Wk : Wv;
    const int k0 = blockIdx.x * 32, n0 = blockIdx.y * 32;
    const int tx = threadIdx.x, ty = threadIdx.y;
    tile[ty][tx] = W[(size_t)(k0 + ty) * CH + n0 + tx];
    __syncthreads();
    const float v = tile[tx][ty];   // = W[k0+tx][n0+ty]
    __nv_bfloat16 h, l;
    split_f32(v, h, l);
    const size_t o = (size_t)blockIdx.z*CH*CH + (size_t)(n0 + ty) * CH + k0 + tx;
    g_wThi[o] = h;
    g_wTlo[o] = l;
}

__global__ void copyx_kernel(const float* __restrict__ x, float* __restrict__ out)
{
    const int i = blockIdx.x * blockDim.x + threadIdx.x;  // float4 index
    if (i >= MTOT * 128) return;
    const int row = i >> 7, c4 = i & 127;
    const float4 val = ((const float4*)x)[(size_t)row * 128 + c4];
    ((float4*)out)[(size_t)row * 256 + c4] = val;
}

// ---------------------------------------------------------------------------
extern "C" void kernel_launch(void* const* d_in, const int* in_sizes, int n_in,
                              void* d_out, int out_size)
{
    const float* x  = (const float*)d_in[0];
    const float* Wq = (const float*)d_in[1];
    const float* bq = (const float*)d_in[2];
    const float* Wk = (const float*)d_in[3];
    const float* bk = (const float*)d_in[4];
    const float* Wv = (const float*)d_in[5];
    const float* bv = (const float*)d_in[6];
    float* out = (float*)d_out;

    cudaFuncSetAttribute(proj_tc,   cudaFuncAttributeMaxDynamicSharedMemorySize, SMEM_TOTAL);
    cudaFuncSetAttribute(scores_tc, cudaFuncAttributeMaxDynamicSharedMemorySize, SMEM_TOTAL);
    cudaFuncSetAttribute(read_tc,   cudaFuncAttributeMaxDynamicSharedMemorySize, SMEM_TOTAL);

    convx_kernel<<<8192, 256>>>(x);
    convw_kernel<<<dim3(16, 16, 3), dim3(32, 32)>>>(Wq, Wk, Wv);
    proj_tc<<<dim3(4, 128, 3), 256, SMEM_TOTAL>>>(bq, bk, bv);
    scores_tc<<<dim3(136, BATCH), 256, SMEM_TOTAL>>>();
    colsum_kernel<<<64, 256>>>();
    convvt_kernel<<<dim3(64, 16, 8), dim3(32, 32)>>>();
    read_tc<<<dim3(4, NTILES, BATCH), 256, SMEM_TOTAL>>>(out);
    copyx_kernel<<<8192, 256>>>(x, out);
}